// round 2
// baseline (speedup 1.0000x reference)
#include <cuda_runtime.h>
#include <cstdint>

#define BB 128
#define TT 100
#define NN 2048
#define OO 512
#define DLY 10

// fp32 constants, matching JAX's double->fp32 constant folding
#define ALPHA_F   0.90483741803595957316f   // exp(-1/10)
#define DEC_F     0.95122942450071400910f   // exp(-1/20)
#define CDEC_F    0.04877057549928599090f   // 1 - exp(-1/20) (folded in double)
#define THRESH_F  0.02f
#define A_PLUS_F  1e-4f
#define A_MINUS_F 1e-4f
#define INVB_F    0.0078125f                // 1/128, exact

// ---------------- state (static device globals; no allocation) ----------------
__device__ float g_v1 [BB*NN];
__device__ float g_tr1[BB*NN];
__device__ float g_v2 [BB*OO];
__device__ float g_vi [BB*OO];
__device__ float g_tr2[BB*OO];
__device__ float g_tri[BB*OO];
__device__ float g_inh[BB*OO];
__device__ float g_buf[BB*DLY*OO];
__device__ float g_hw [OO*NN];
__device__ float g_iew[OO*OO];
__device__ float g_ediag[OO];
__device__ float g_mtr2[OO];
__device__ int   g_nzcnt[NN];
__device__ int   g_nzcol[NN*NN];
__device__ float g_nzval[NN*NN];

// ---------------- init: reset state each launch (graph replays!) ----------------
__global__ void k_init(const float* __restrict__ hw_in,
                       const float* __restrict__ eiw_in,
                       const float* __restrict__ iew_in) {
    int i = blockIdx.x * blockDim.x + threadIdx.x;   // grid covers OO*NN
    if (i < OO*NN) g_hw[i] = hw_in[i];
    if (i < BB*DLY*OO) g_buf[i] = 0.f;
    if (i < BB*NN) { g_v1[i] = 0.f; g_tr1[i] = 0.f; }
    if (i < BB*OO) { g_v2[i]=0.f; g_vi[i]=0.f; g_tr2[i]=0.f; g_tri[i]=0.f; g_inh[i]=0.f; }
    if (i < OO*OO) { int r = i / OO, c = i - r*OO; g_iew[i] = (r == c) ? 0.f : iew_in[i]; }
    if (i < OO) g_ediag[i] = eiw_in[i*OO + i];
}

// ---------------- CSR build of input_weight (warp per row) ----------------
__global__ void k_csr(const float* __restrict__ W) {
    int wid  = (blockIdx.x * blockDim.x + threadIdx.x) >> 5;
    int lane = threadIdx.x & 31;
    if (wid >= NN) return;
    int cnt = 0;
    for (int base = 0; base < NN; base += 32) {
        float w = W[wid*NN + base + lane];
        unsigned m = __ballot_sync(0xffffffffu, w != 0.f);
        if (w != 0.f) {
            int pos = cnt + __popc(m & ((1u << lane) - 1u));
            g_nzcol[(size_t)wid*NN + pos] = base + lane;
            g_nzval[(size_t)wid*NN + pos] = w;
        }
        cnt += __popc(m);
    }
    if (lane == 0) g_nzcnt[wid] = cnt;
}

// ---------------- layer 1 LIF + trace + output (elementwise) ----------------
__global__ __launch_bounds__(256) void k_layer1(const float* __restrict__ x,
                                                float* __restrict__ out_l1, int t) {
    int idx = blockIdx.x * 256 + threadIdx.x;      // grid == BB*NN exactly
    int b = idx >> 11;
    int n = idx & (NN - 1);
    const float* xr = x + ((size_t)b*TT + t) * NN;
    int cnt = g_nzcnt[n];
    const int*   cp = g_nzcol + (size_t)n*NN;
    const float* vp = g_nzval + (size_t)n*NN;
    float acc = 0.f;
    for (int j = 0; j < cnt; j++) acc = fmaf(xr[cp[j]], vp[j], acc);
    // XLA contracts ALPHA*v + inp into a single fma
    float v = fmaf(ALPHA_F, g_v1[idx], acc);
    float s = (v > THRESH_F) ? 1.f : 0.f;
    g_v1[idx]  = (v > THRESH_F) ? 0.f : v;
    // tr = fma(DEC, tr, (1-DEC)*s); (1-DEC)*s exact for s in {0,1}
    g_tr1[idx] = fmaf(DEC_F, g_tr1[idx], __fmul_rn(CDEC_F, s));
    out_l1[((size_t)b*TT + t) * NN + n] = s;
}

// ---------------- phase2: l1v GEMM + inh_out GEMM + l2 LIF + inh LIF + traces ----------------
// grid: x = 8 q-tiles (64 q each), y = 32 b-tiles (4 b each); 256 threads.
__global__ __launch_bounds__(256) void k_phase2(const float* __restrict__ out_l1,
                                                float* __restrict__ out_l2,
                                                int t, int tm) {
    __shared__ __align__(16) float s_l1 [4][NN];
    __shared__ __align__(16) float s_buf[4][OO];
    int tid = threadIdx.x;
    int b0  = blockIdx.y * 4;
    int qt  = blockIdx.x;

    #pragma unroll
    for (int i = 0; i < 8; i++) {
        int f = tid + i*256; int r = f >> 9; int c4 = (f & 511) * 4;
        *(float4*)&s_l1[r][c4] = *(const float4*)&out_l1[((size_t)(b0 + r)*TT + t)*NN + c4];
    }
    #pragma unroll
    for (int i = 0; i < 2; i++) {
        int f = tid + i*256; int r = f >> 7; int c4 = (f & 127) * 4;
        *(float4*)&s_buf[r][c4] = *(const float4*)&g_buf[((size_t)(b0 + r)*DLY + tm)*OO + c4];
    }
    __syncthreads();

    int w = tid >> 5, lane = tid & 31;
    const float4* sl0 = (const float4*)s_l1[0];
    const float4* sl1 = (const float4*)s_l1[1];
    const float4* sl2 = (const float4*)s_l1[2];
    const float4* sl3 = (const float4*)s_l1[3];
    const float4* sb0 = (const float4*)s_buf[0];
    const float4* sb1 = (const float4*)s_buf[1];
    const float4* sb2 = (const float4*)s_buf[2];
    const float4* sb3 = (const float4*)s_buf[3];

    for (int qq = 0; qq < 8; qq++) {
        int q = qt*64 + w*8 + qq;
        const float4* hw4 = (const float4*)(g_hw + (size_t)q*NN);
        float4 A0 = {0,0,0,0}, A1 = {0,0,0,0}, A2 = {0,0,0,0}, A3 = {0,0,0,0};
        for (int kk = lane; kk < 512; kk += 32) {
            float4 wv = hw4[kk];
            float4 x0 = sl0[kk], x1 = sl1[kk], x2 = sl2[kk], x3 = sl3[kk];
            A0.x = fmaf(wv.x, x0.x, A0.x); A0.y = fmaf(wv.y, x0.y, A0.y);
            A0.z = fmaf(wv.z, x0.z, A0.z); A0.w = fmaf(wv.w, x0.w, A0.w);
            A1.x = fmaf(wv.x, x1.x, A1.x); A1.y = fmaf(wv.y, x1.y, A1.y);
            A1.z = fmaf(wv.z, x1.z, A1.z); A1.w = fmaf(wv.w, x1.w, A1.w);
            A2.x = fmaf(wv.x, x2.x, A2.x); A2.y = fmaf(wv.y, x2.y, A2.y);
            A2.z = fmaf(wv.z, x2.z, A2.z); A2.w = fmaf(wv.w, x2.w, A2.w);
            A3.x = fmaf(wv.x, x3.x, A3.x); A3.y = fmaf(wv.y, x3.y, A3.y);
            A3.z = fmaf(wv.z, x3.z, A3.z); A3.w = fmaf(wv.w, x3.w, A3.w);
        }
        float m0 = ((A0.x + A0.y) + A0.z) + A0.w;
        float m1 = ((A1.x + A1.y) + A1.z) + A1.w;
        float m2 = ((A2.x + A2.y) + A2.z) + A2.w;
        float m3 = ((A3.x + A3.y) + A3.z) + A3.w;

        const float4* iw4 = (const float4*)(g_iew + (size_t)q*OO);
        float4 I0 = {0,0,0,0}, I1 = {0,0,0,0}, I2 = {0,0,0,0}, I3 = {0,0,0,0};
        for (int kk = lane; kk < 128; kk += 32) {
            float4 wv = iw4[kk];
            float4 x0 = sb0[kk], x1 = sb1[kk], x2 = sb2[kk], x3 = sb3[kk];
            I0.x = fmaf(wv.x, x0.x, I0.x); I0.y = fmaf(wv.y, x0.y, I0.y);
            I0.z = fmaf(wv.z, x0.z, I0.z); I0.w = fmaf(wv.w, x0.w, I0.w);
            I1.x = fmaf(wv.x, x1.x, I1.x); I1.y = fmaf(wv.y, x1.y, I1.y);
            I1.z = fmaf(wv.z, x1.z, I1.z); I1.w = fmaf(wv.w, x1.w, I1.w);
            I2.x = fmaf(wv.x, x2.x, I2.x); I2.y = fmaf(wv.y, x2.y, I2.y);
            I2.z = fmaf(wv.z, x2.z, I2.z); I2.w = fmaf(wv.w, x2.w, I2.w);
            I3.x = fmaf(wv.x, x3.x, I3.x); I3.y = fmaf(wv.y, x3.y, I3.y);
            I3.z = fmaf(wv.z, x3.z, I3.z); I3.w = fmaf(wv.w, x3.w, I3.w);
        }
        float i0 = ((I0.x + I0.y) + I0.z) + I0.w;
        float i1 = ((I1.x + I1.y) + I1.z) + I1.w;
        float i2 = ((I2.x + I2.y) + I2.z) + I2.w;
        float i3 = ((I3.x + I3.y) + I3.z) + I3.w;

        #pragma unroll
        for (int off = 16; off > 0; off >>= 1) {
            m0 += __shfl_xor_sync(0xffffffffu, m0, off);
            m1 += __shfl_xor_sync(0xffffffffu, m1, off);
            m2 += __shfl_xor_sync(0xffffffffu, m2, off);
            m3 += __shfl_xor_sync(0xffffffffu, m3, off);
            i0 += __shfl_xor_sync(0xffffffffu, i0, off);
            i1 += __shfl_xor_sync(0xffffffffu, i1, off);
            i2 += __shfl_xor_sync(0xffffffffu, i2, off);
            i3 += __shfl_xor_sync(0xffffffffu, i3, off);
        }

        if (lane < 4) {
            float l1v = (lane == 0) ? m0 : (lane == 1) ? m1 : (lane == 2) ? m2 : m3;
            float io  = (lane == 0) ? i0 : (lane == 1) ? i1 : (lane == 2) ? i2 : i3;
            int bg = b0 + lane;
            int bo = bg*OO + q;
            float inp = __fadd_rn(l1v, -io);
            // v2 = fma(ALPHA, v2, (l1v - inh_out))
            float v = fmaf(ALPHA_F, g_v2[bo], inp);
            float s = (v > THRESH_F) ? 1.f : 0.f;
            g_v2[bo] = (v > THRESH_F) ? 0.f : v;
            out_l2[((size_t)bg*TT + t)*OO + q] = s;
            g_tr2[bo] = fmaf(DEC_F, g_tr2[bo], __fmul_rn(CDEC_F, s));
            // inh layer: eiw masked to diagonal each step -> inh_in = l2[b,q]*ediag[q] (exact)
            float inh_in = __fmul_rn(s, g_ediag[q]);
            float vv = fmaf(ALPHA_F, g_vi[bo], inh_in);
            float si = (vv > THRESH_F) ? 1.f : 0.f;
            g_vi[bo]  = (vv > THRESH_F) ? 0.f : vv;
            g_inh[bo] = si;
            g_tri[bo] = fmaf(DEC_F, g_tri[bo], __fmul_rn(CDEC_F, si));
        }
    }
}

// ---------------- per-q reductions + ediag update + deferred buf write ----------------
__global__ void k_reduce(int tm) {
    int i = blockIdx.x * blockDim.x + threadIdx.x;
    if (i < OO) {
        int q = i;
        float s2 = 0.f, si = 0.f, sd = 0.f;
        for (int b = 0; b < BB; b++) {
            float t2 = g_tr2[b*OO + q];
            float ti = g_tri[b*OO + q];
            s2 += t2; si += ti; sd = fmaf(ti, t2, sd);   // hebb diag: tri(post)*tr2(pre)
        }
        float m2 = s2 * INVB_F;
        float mi = si * INVB_F;
        g_mtr2[q] = m2;
        float e = g_ediag[q];
        // dw = fma(A+, hebb, -((A- * e) * mi)); e += dw
        float dw = fmaf(A_PLUS_F, __fmul_rn(sd, INVB_F),
                        -__fmul_rn(__fmul_rn(A_MINUS_F, e), mi));
        g_ediag[q] = __fadd_rn(e, dw);
    } else if (i < OO + BB*OO) {
        int j = i - OO;
        int b = j >> 9;
        int q = j & (OO - 1);
        g_buf[((size_t)b*DLY + tm)*OO + q] = g_inh[j];
    }
}

// ---------------- plasticity GEMM: W[q,p] += A+*mean_b(post[b,q]*pre[b,p]) - A-*W*mean(post)[q]
// mode 0: hw (pre=tr1, P=NN);  mode 1: iew (pre=tri, P=OO, diag masked to 0)
__global__ __launch_bounds__(256) void k_plast(int mode) {
    const float* post = g_tr2;
    const float* pre  = (mode == 0) ? g_tr1 : g_tri;
    float*       W    = (mode == 0) ? g_hw  : g_iew;
    const int    P    = (mode == 0) ? NN    : OO;
    const int    msk  = mode;

    int pb = blockIdx.x * 64;
    int qb = blockIdx.y * 64;
    __shared__ __align__(16) float sa[64][64];   // [k][q]  (post)
    __shared__ __align__(16) float sb[64][64];   // [k][p]  (pre)
    int tid = threadIdx.x;
    int tx = tid & 15, ty = tid >> 4;
    float acc[4][4] = {};

    for (int kc = 0; kc < BB; kc += 64) {
        __syncthreads();
        #pragma unroll
        for (int i = 0; i < 4; i++) {
            int f = tid + i*256; int k = f >> 4; int c4 = (f & 15) * 4;
            *(float4*)&sa[k][c4] = *(const float4*)&post[(size_t)(kc + k)*OO + qb + c4];
            *(float4*)&sb[k][c4] = *(const float4*)&pre [(size_t)(kc + k)*P  + pb + c4];
        }
        __syncthreads();
        #pragma unroll 16
        for (int k = 0; k < 64; k++) {
            float4 a = *(const float4*)&sa[k][ty*4];
            float4 b = *(const float4*)&sb[k][tx*4];
            float av[4] = {a.x, a.y, a.z, a.w};
            float bv[4] = {b.x, b.y, b.z, b.w};
            #pragma unroll
            for (int iq = 0; iq < 4; iq++)
                #pragma unroll
                for (int ip = 0; ip < 4; ip++)
                    acc[iq][ip] = fmaf(av[iq], bv[ip], acc[iq][ip]);
        }
    }

    int q0 = qb + ty*4, p0 = pb + tx*4;
    #pragma unroll
    for (int iq = 0; iq < 4; iq++) {
        int q = q0 + iq;
        float mean = g_mtr2[q];
        #pragma unroll
        for (int ip = 0; ip < 4; ip++) {
            size_t idx = (size_t)q*P + p0 + ip;
            float w  = W[idx];
            // dw = fma(A+, hebb_mean, -((A- * w) * mean)); w += dw
            float dw = fmaf(A_PLUS_F, __fmul_rn(acc[iq][ip], INVB_F),
                            -__fmul_rn(__fmul_rn(A_MINUS_F, w), mean));
            float nw = __fadd_rn(w, dw);
            if (msk && q == (p0 + ip)) nw = 0.f;
            W[idx] = nw;
        }
    }
}

// ---------------- launch ----------------
extern "C" void kernel_launch(void* const* d_in, const int* in_sizes, int n_in,
                              void* d_out, int out_size) {
    const float* x      = (const float*)d_in[0];
    const float* win    = (const float*)d_in[1];
    const float* hw_in  = (const float*)d_in[2];
    const float* eiw_in = (const float*)d_in[3];
    const float* iew_in = (const float*)d_in[4];
    float* out_l1 = (float*)d_out;
    float* out_l2 = out_l1 + (size_t)BB*TT*NN;

    k_init<<<(OO*NN)/256, 256>>>(hw_in, eiw_in, iew_in);
    k_csr<<<256, 256>>>(win);

    for (int t = 0; t < TT; t++) {
        int tm = t % DLY;
        k_layer1<<<(BB*NN)/256, 256>>>(x, out_l1, t);
        k_phase2<<<dim3(8, 32), 256>>>(out_l1, out_l2, t, tm);
        k_reduce<<<(OO + BB*OO + 255)/256, 256>>>(tm);
        k_plast<<<dim3(NN/64, OO/64), 256>>>(0);   // hw
        k_plast<<<dim3(OO/64, OO/64), 256>>>(1);   // iew
    }
}

// round 3
// speedup vs baseline: 1.5418x; 1.5418x over previous
#include <cuda_runtime.h>
#include <cstdint>

#define BB 128
#define TT 100
#define NN 2048
#define OO 512
#define DLY 10

#define ALPHA_F   0.90483741803595957316f   // exp(-1/10)
#define DEC_F     0.95122942450071400910f   // exp(-1/20)
#define CDEC_F    0.04877057549928599090f   // 1 - exp(-1/20)
#define THRESH_F  0.02f
#define A_PLUS_F  1e-4f
#define A_MINUS_F 1e-4f
#define INVB_F    0.0078125f                // 1/128, exact

#define SPLIT_A 16          // hw K-chunks of 128 (K=2048)
#define SPLIT_I 4           // iew K-chunks of 128 (K=512)

// ---------------- state (static device globals; no allocation) ----------------
__device__ float g_v1 [BB*NN];
__device__ float g_tr1[BB*NN];
__device__ float g_v2 [BB*OO];
__device__ float g_vi [BB*OO];
__device__ float g_tr2[BB*OO];
__device__ float g_tri[BB*OO];
__device__ float g_buf[BB*DLY*OO];
__device__ float g_hw [OO*NN];
__device__ float g_iew[OO*OO];
__device__ float g_ediag[OO];
__device__ float g_mtr2[OO];
__device__ float g_pA[SPLIT_A*BB*OO];
__device__ float g_pI[SPLIT_I*BB*OO];
__device__ int   g_nzcnt[NN];
__device__ int   g_nzcol[NN*NN];
__device__ float g_nzval[NN*NN];

// ---------------- init: reset state each launch (graph replays!) ----------------
__global__ void k_init(const float* __restrict__ hw_in,
                       const float* __restrict__ eiw_in,
                       const float* __restrict__ iew_in) {
    int i = blockIdx.x * blockDim.x + threadIdx.x;   // grid covers OO*NN
    if (i < OO*NN) g_hw[i] = hw_in[i];
    if (i < BB*DLY*OO) g_buf[i] = 0.f;
    if (i < BB*NN) { g_v1[i] = 0.f; g_tr1[i] = 0.f; }
    if (i < BB*OO) { g_v2[i]=0.f; g_vi[i]=0.f; g_tr2[i]=0.f; g_tri[i]=0.f; }
    if (i < OO*OO) { int r = i / OO, c = i - r*OO; g_iew[i] = (r == c) ? 0.f : iew_in[i]; }
    if (i < OO) g_ediag[i] = eiw_in[i*OO + i];
}

// ---------------- CSR build of input_weight (warp per row) ----------------
__global__ void k_csr(const float* __restrict__ W) {
    int wid  = (blockIdx.x * blockDim.x + threadIdx.x) >> 5;
    int lane = threadIdx.x & 31;
    if (wid >= NN) return;
    int cnt = 0;
    for (int base = 0; base < NN; base += 32) {
        float w = W[wid*NN + base + lane];
        unsigned m = __ballot_sync(0xffffffffu, w != 0.f);
        if (w != 0.f) {
            int pos = cnt + __popc(m & ((1u << lane) - 1u));
            g_nzcol[(size_t)wid*NN + pos] = base + lane;
            g_nzval[(size_t)wid*NN + pos] = w;
        }
        cnt += __popc(m);
    }
    if (lane == 0) g_nzcnt[wid] = cnt;
}

// ---------------- layer 1 LIF + trace + output (elementwise) ----------------
__global__ __launch_bounds__(256) void k_layer1(const float* __restrict__ x,
                                                float* __restrict__ out_l1, int t) {
    int idx = blockIdx.x * 256 + threadIdx.x;      // grid == BB*NN exactly
    int b = idx >> 11;
    int n = idx & (NN - 1);
    const float* xr = x + ((size_t)b*TT + t) * NN;
    int cnt = g_nzcnt[n];
    const int*   cp = g_nzcol + (size_t)n*NN;
    const float* vp = g_nzval + (size_t)n*NN;
    float acc = 0.f;
    for (int j = 0; j < cnt; j++) acc = fmaf(xr[cp[j]], vp[j], acc);
    float v = fmaf(ALPHA_F, g_v1[idx], acc);
    float s = (v > THRESH_F) ? 1.f : 0.f;
    g_v1[idx]  = (v > THRESH_F) ? 0.f : v;
    g_tr1[idx] = fmaf(DEC_F, g_tr1[idx], __fmul_rn(CDEC_F, s));
    out_l1[((size_t)b*TT + t) * NN + n] = s;
}

// ---------------- split-K partial GEMM: 64b x 64q tile, K-chunk 128 ----------------
// blockIdx: x = q-tile (8), y = b-tile (2), z = split 0..(SPLIT_A+SPLIT_I-1)
__global__ __launch_bounds__(256) void k_gemm(const float* __restrict__ out_l1, int t, int tm) {
    __shared__ __align__(16) float sa[32][68];   // [k][b]
    __shared__ __align__(16) float sb[32][68];   // [k][q]
    int z = blockIdx.z;
    const float* pre; size_t pre_stride; const float* W; int wstride; float* part; int k0;
    if (z < SPLIT_A) {
        pre = out_l1 + (size_t)t*NN; pre_stride = (size_t)TT*NN;
        W = g_hw; wstride = NN; part = g_pA + (size_t)z*BB*OO; k0 = z*128;
    } else {
        pre = g_buf + (size_t)tm*OO; pre_stride = (size_t)DLY*OO;
        W = g_iew; wstride = OO; part = g_pI + (size_t)(z-SPLIT_A)*BB*OO; k0 = (z-SPLIT_A)*128;
    }
    int b0 = blockIdx.y * 64, q0 = blockIdx.x * 64;
    int tid = threadIdx.x;
    int lr = tid >> 3;          // 0..31 (row within half-tile)
    int kq = tid & 7;           // float4 index along k
    int tx = tid & 15, ty = tid >> 4;

    float acc00=0,acc01=0,acc02=0,acc03=0, acc10=0,acc11=0,acc12=0,acc13=0;
    float acc20=0,acc21=0,acc22=0,acc23=0, acc30=0,acc31=0,acc32=0,acc33=0;

    for (int kc = 0; kc < 128; kc += 32) {
        int kg = k0 + kc + kq*4;
        float4 a0 = *(const float4*)(pre + (size_t)(b0+lr)*pre_stride + kg);
        float4 a1 = *(const float4*)(pre + (size_t)(b0+lr+32)*pre_stride + kg);
        float4 w0 = *(const float4*)(W + (size_t)(q0+lr)*wstride + kg);
        float4 w1 = *(const float4*)(W + (size_t)(q0+lr+32)*wstride + kg);
        __syncthreads();
        sa[kq*4+0][lr]    = a0.x; sa[kq*4+1][lr]    = a0.y; sa[kq*4+2][lr]    = a0.z; sa[kq*4+3][lr]    = a0.w;
        sa[kq*4+0][lr+32] = a1.x; sa[kq*4+1][lr+32] = a1.y; sa[kq*4+2][lr+32] = a1.z; sa[kq*4+3][lr+32] = a1.w;
        sb[kq*4+0][lr]    = w0.x; sb[kq*4+1][lr]    = w0.y; sb[kq*4+2][lr]    = w0.z; sb[kq*4+3][lr]    = w0.w;
        sb[kq*4+0][lr+32] = w1.x; sb[kq*4+1][lr+32] = w1.y; sb[kq*4+2][lr+32] = w1.z; sb[kq*4+3][lr+32] = w1.w;
        __syncthreads();
        #pragma unroll
        for (int k = 0; k < 32; k++) {
            float4 av = *(const float4*)&sa[k][ty*4];
            float4 wv = *(const float4*)&sb[k][tx*4];
            acc00 = fmaf(av.x, wv.x, acc00); acc01 = fmaf(av.x, wv.y, acc01);
            acc02 = fmaf(av.x, wv.z, acc02); acc03 = fmaf(av.x, wv.w, acc03);
            acc10 = fmaf(av.y, wv.x, acc10); acc11 = fmaf(av.y, wv.y, acc11);
            acc12 = fmaf(av.y, wv.z, acc12); acc13 = fmaf(av.y, wv.w, acc13);
            acc20 = fmaf(av.z, wv.x, acc20); acc21 = fmaf(av.z, wv.y, acc21);
            acc22 = fmaf(av.z, wv.z, acc22); acc23 = fmaf(av.z, wv.w, acc23);
            acc30 = fmaf(av.w, wv.x, acc30); acc31 = fmaf(av.w, wv.y, acc31);
            acc32 = fmaf(av.w, wv.z, acc32); acc33 = fmaf(av.w, wv.w, acc33);
        }
    }
    float* p = part + (size_t)(b0 + ty*4)*OO + q0 + tx*4;
    float4 o;
    o.x=acc00; o.y=acc01; o.z=acc02; o.w=acc03; *(float4*)(p + 0*OO) = o;
    o.x=acc10; o.y=acc11; o.z=acc12; o.w=acc13; *(float4*)(p + 1*OO) = o;
    o.x=acc20; o.y=acc21; o.z=acc22; o.w=acc23; *(float4*)(p + 2*OO) = o;
    o.x=acc30; o.y=acc31; o.z=acc32; o.w=acc33; *(float4*)(p + 3*OO) = o;
}

// ---------------- epilogue: chunk-sum + l2/inh LIF + traces + buf + per-q reductions ----------------
// grid 32 blocks x 256 threads; block covers 16 q x all 128 b
__global__ __launch_bounds__(256) void k_epi(float* __restrict__ out_l2, int t, int tm) {
    int qb = blockIdx.x * 16;
    int tq = threadIdx.x & 15;
    int tb = threadIdx.x >> 4;       // 0..15
    int q  = qb + tq;
    __shared__ float sh[3][16][16];

    float r2 = 0.f, ri = 0.f, rd = 0.f;
    for (int j = 0; j < 8; j++) {
        int b  = tb + 16*j;
        int bo = b*OO + q;
        float l1v = 0.f, io = 0.f;
        #pragma unroll
        for (int s = 0; s < SPLIT_A; s++) l1v = __fadd_rn(l1v, g_pA[(size_t)s*BB*OO + bo]);
        #pragma unroll
        for (int s = 0; s < SPLIT_I; s++) io  = __fadd_rn(io,  g_pI[(size_t)s*BB*OO + bo]);
        float v = fmaf(ALPHA_F, g_v2[bo], __fadd_rn(l1v, -io));
        float s2 = (v > THRESH_F) ? 1.f : 0.f;
        g_v2[bo] = (v > THRESH_F) ? 0.f : v;
        out_l2[((size_t)b*TT + t)*OO + q] = s2;
        float t2 = fmaf(DEC_F, g_tr2[bo], __fmul_rn(CDEC_F, s2));
        g_tr2[bo] = t2;
        float inh_in = __fmul_rn(s2, g_ediag[q]);
        float vv = fmaf(ALPHA_F, g_vi[bo], inh_in);
        float si = (vv > THRESH_F) ? 1.f : 0.f;
        g_vi[bo] = (vv > THRESH_F) ? 0.f : vv;
        g_buf[((size_t)b*DLY + tm)*OO + q] = si;
        float ti = fmaf(DEC_F, g_tri[bo], __fmul_rn(CDEC_F, si));
        g_tri[bo] = ti;
        r2 += t2; ri += ti; rd = fmaf(ti, t2, rd);
    }
    sh[0][tb][tq] = r2; sh[1][tb][tq] = ri; sh[2][tb][tq] = rd;
    __syncthreads();
    if (tb == 0) {
        float s2 = 0.f, si = 0.f, sd = 0.f;
        for (int g = 0; g < 16; g++) { s2 += sh[0][g][tq]; si += sh[1][g][tq]; sd += sh[2][g][tq]; }
        float m2 = s2 * INVB_F, mi = si * INVB_F;
        g_mtr2[q] = m2;
        float e = g_ediag[q];
        float dw = fmaf(A_PLUS_F, __fmul_rn(sd, INVB_F),
                        -__fmul_rn(__fmul_rn(A_MINUS_F, e), mi));
        g_ediag[q] = __fadd_rn(e, dw);
    }
}

// ---------------- plasticity GEMM (both weight matrices in one launch) ----------------
// grid.x: 0..31 -> hw p-tiles; 32..39 -> iew p-tiles. grid.y: q-tiles (8).
__global__ __launch_bounds__(256) void k_plast() {
    int bx = blockIdx.x;
    int mode = (bx >= NN/64);
    const float* post = g_tr2;
    const float* pre  = mode ? g_tri : g_tr1;
    float*       W    = mode ? g_iew : g_hw;
    const int    P    = mode ? OO    : NN;

    int pb = (mode ? (bx - NN/64) : bx) * 64;
    int qb = blockIdx.y * 64;
    __shared__ __align__(16) float sa[64][64];   // [k][q]  (post)
    __shared__ __align__(16) float sb[64][64];   // [k][p]  (pre)
    int tid = threadIdx.x;
    int tx = tid & 15, ty = tid >> 4;
    float acc[4][4] = {};

    for (int kc = 0; kc < BB; kc += 64) {
        __syncthreads();
        #pragma unroll
        for (int i = 0; i < 4; i++) {
            int f = tid + i*256; int k = f >> 4; int c4 = (f & 15) * 4;
            *(float4*)&sa[k][c4] = *(const float4*)&post[(size_t)(kc + k)*OO + qb + c4];
            *(float4*)&sb[k][c4] = *(const float4*)&pre [(size_t)(kc + k)*P  + pb + c4];
        }
        __syncthreads();
        #pragma unroll 16
        for (int k = 0; k < 64; k++) {
            float4 a = *(const float4*)&sa[k][ty*4];
            float4 b = *(const float4*)&sb[k][tx*4];
            float av[4] = {a.x, a.y, a.z, a.w};
            float bv[4] = {b.x, b.y, b.z, b.w};
            #pragma unroll
            for (int iq = 0; iq < 4; iq++)
                #pragma unroll
                for (int ip = 0; ip < 4; ip++)
                    acc[iq][ip] = fmaf(av[iq], bv[ip], acc[iq][ip]);
        }
    }

    int q0 = qb + ty*4, p0 = pb + tx*4;
    #pragma unroll
    for (int iq = 0; iq < 4; iq++) {
        int q = q0 + iq;
        float mean = g_mtr2[q];
        #pragma unroll
        for (int ip = 0; ip < 4; ip++) {
            size_t idx = (size_t)q*P + p0 + ip;
            float w  = W[idx];
            float dw = fmaf(A_PLUS_F, __fmul_rn(acc[iq][ip], INVB_F),
                            -__fmul_rn(__fmul_rn(A_MINUS_F, w), mean));
            float nw = __fadd_rn(w, dw);
            if (mode && q == (p0 + ip)) nw = 0.f;
            W[idx] = nw;
        }
    }
}

// ---------------- launch ----------------
extern "C" void kernel_launch(void* const* d_in, const int* in_sizes, int n_in,
                              void* d_out, int out_size) {
    const float* x      = (const float*)d_in[0];
    const float* win    = (const float*)d_in[1];
    const float* hw_in  = (const float*)d_in[2];
    const float* eiw_in = (const float*)d_in[3];
    const float* iew_in = (const float*)d_in[4];
    float* out_l1 = (float*)d_out;
    float* out_l2 = out_l1 + (size_t)BB*TT*NN;

    k_init<<<(OO*NN)/256, 256>>>(hw_in, eiw_in, iew_in);
    k_csr<<<256, 256>>>(win);

    for (int t = 0; t < TT; t++) {
        int tm = t % DLY;
        k_layer1<<<(BB*NN)/256, 256>>>(x, out_l1, t);
        k_gemm<<<dim3(8, 2, SPLIT_A + SPLIT_I), 256>>>(out_l1, t, tm);
        k_epi<<<32, 256>>>(out_l2, t, tm);
        k_plast<<<dim3(NN/64 + OO/64, OO/64), 256>>>();
    }
}